// round 4
// baseline (speedup 1.0000x reference)
#include <cuda_runtime.h>

// field[i,j] = sum_n w_n * ox_n[i] * oy_n[j] / (lx*ly)
// dims < 3/G per axis -> each rect overlaps at most 4 consecutive cells per axis.
// 4 threads per rect: each thread owns one footprint row (i), does <=4 REDs.
// Grid-constant reciprocals via MUFU (exact here: lx = 1/256).

#define G 256

__global__ void zero_field_kernel4(float4* __restrict__ out, int n4) {
    int i = blockIdx.x * blockDim.x + threadIdx.x;
    if (i < n4) out[i] = make_float4(0.f, 0.f, 0.f, 0.f);
}

__global__ void __launch_bounds__(256) charge_scatter_kernel(
    const float4* __restrict__ boundary,  // [xmin, ymin, xmax, ymax]
    const float2* __restrict__ xy,        // [N]
    const float2* __restrict__ dims,      // [N]
    const float* __restrict__ cw,         // [N]
    float* __restrict__ field,            // [G*G]
    int n)
{
    int t = blockIdx.x * blockDim.x + threadIdx.x;
    int r = t >> 2;          // rect index
    int rowsel = t & 3;      // which footprint row this thread owns
    if (r >= n) return;

    const float4 b = *boundary;
    const float xmin = b.x, ymin = b.y;
    const float lx = (b.z - b.x) * (1.0f / G);
    const float ly = (b.w - b.y) * (1.0f / G);
    const float inv_lx = __frcp_rn(lx);   // single MUFU, exact for lx = 2^-8
    const float inv_ly = __frcp_rn(ly);

    const float2 p = xy[r];
    const float2 d = dims[r];
    const float bx0 = p.x;
    const float by0 = p.y;
    const float bx1 = bx0 + d.x;
    const float by1 = by0 + d.y;

    int i0 = (int)floorf((bx0 - xmin) * inv_lx);
    int j0 = (int)floorf((by0 - ymin) * inv_ly);
    i0 = max(i0, 0);
    j0 = max(j0, 0);

    const int i = i0 + rowsel;
    if (i >= G) return;

    // x overlap for this thread's row
    const float gx0 = xmin + (float)i * lx;
    const float ox = fmaxf(fminf(gx0 + lx, bx1) - fmaxf(gx0, bx0), 0.0f);
    const float sx = cw[r] * inv_lx * inv_ly * ox;
    if (sx == 0.0f) return;   // row outside footprint (e.g. 4th row of a 3-row rect)

    float* row = field + i * G + j0;
    const float gy0base = ymin + (float)j0 * ly;

    #pragma unroll
    for (int jj = 0; jj < 4; jj++) {
        float gy0 = gy0base + (float)jj * ly;
        float oy = fmaxf(fminf(gy0 + ly, by1) - fmaxf(gy0, by0), 0.0f);
        float v = sx * oy;
        if ((j0 + jj) < G && v != 0.0f) atomicAdd(row + jj, v);
    }
}

extern "C" void kernel_launch(void* const* d_in, const int* in_sizes, int n_in,
                              void* d_out, int out_size) {
    const float4* boundary = (const float4*)d_in[0];
    const float2* xy       = (const float2*)d_in[1];
    const float2* dims     = (const float2*)d_in[2];
    const float*  cw       = (const float*)d_in[3];
    float* field = (float*)d_out;

    const int n = in_sizes[3];          // N_RECTS

    // d_out is poisoned; zero it (vectorized).
    int n4 = out_size / 4;
    zero_field_kernel4<<<(n4 + 255) / 256, 256>>>((float4*)field, n4);

    // 4 threads per rect (one per footprint row)
    long long threads_total = 4LL * n;
    int blocks = (int)((threads_total + 255) / 256);
    charge_scatter_kernel<<<blocks, 256>>>(boundary, xy, dims, cw, field, n);
}

// round 6
// speedup vs baseline: 1.1359x; 1.1359x over previous
#include <cuda_runtime.h>

// field[i,j] = sum_n w_n * ox_n[i] * oy_n[j] / (lx*ly)
// dims < 3/G per axis -> each rect overlaps at most 4 consecutive cells per axis.
// 2 threads per rect (R2 topology, best measured): each thread owns a 2-wide
// j-half of the <=4x4 footprint. Thread pairs hit adjacent addresses -> REDs
// coalesce into the same L2 sector.
// R4 change: __frcp_rn instead of div.rn (exact: lx = 2^-8), tighter loop bounds.

#define G 256

__global__ void zero_field_kernel4(float4* __restrict__ out, int n4) {
    int i = blockIdx.x * blockDim.x + threadIdx.x;
    if (i < n4) out[i] = make_float4(0.f, 0.f, 0.f, 0.f);
}

__global__ void __launch_bounds__(256) charge_scatter_kernel(
    const float4* __restrict__ boundary,  // [xmin, ymin, xmax, ymax]
    const float2* __restrict__ xy,        // [N]
    const float2* __restrict__ dims,      // [N]
    const float* __restrict__ cw,         // [N]
    float* __restrict__ field,            // [G*G]
    int n)
{
    int t = blockIdx.x * blockDim.x + threadIdx.x;
    int r = t >> 1;          // rect index
    int half = t & 1;        // which 2-column j-half of the footprint
    if (r >= n) return;

    const float4 b = *boundary;
    const float xmin = b.x, ymin = b.y;
    const float lx = (b.z - b.x) * (1.0f / G);
    const float ly = (b.w - b.y) * (1.0f / G);
    const float inv_lx = __frcp_rn(lx);   // 1 MUFU; exact for lx = 2^-8
    const float inv_ly = __frcp_rn(ly);

    const float2 p = xy[r];
    const float2 d = dims[r];
    const float bx0 = p.x;
    const float by0 = p.y;
    const float bx1 = bx0 + d.x;
    const float by1 = by0 + d.y;
    const float scale = cw[r] * inv_lx * inv_ly;

    int i0 = (int)floorf((bx0 - xmin) * inv_lx);
    int j0 = (int)floorf((by0 - ymin) * inv_ly);
    i0 = max(i0, 0);
    j0 = max(j0, 0);
    const int i1 = min(i0 + 3, G - 1);   // clamp upper bound once

    // This thread's two j cells
    const int jA = j0 + half * 2;
    const bool jA_ok = (jA < G);
    const bool jB_ok = (jA + 1 < G);

    // y overlaps for the two cells
    float oy0, oy1;
    {
        float gy0 = ymin + (float)jA * ly;
        float gy1 = gy0 + ly;
        oy0 = fmaxf(fminf(gy1, by1) - fmaxf(gy0, by0), 0.0f);
        oy1 = fmaxf(fminf(gy1 + ly, by1) - fmaxf(gy1, by0), 0.0f);
    }
    if (!jA_ok || (oy0 == 0.0f && oy1 == 0.0f)) return;

    for (int i = i0; i <= i1; i++) {
        float gx0 = xmin + (float)i * lx;
        float ox = fmaxf(fminf(gx0 + lx, bx1) - fmaxf(gx0, bx0), 0.0f);
        float sx = scale * ox;
        float v0 = sx * oy0;
        float v1 = sx * oy1;
        float* row = field + i * G + jA;
        if (v0 != 0.0f) atomicAdd(row, v0);
        if (jB_ok && v1 != 0.0f) atomicAdd(row + 1, v1);
    }
}

extern "C" void kernel_launch(void* const* d_in, const int* in_sizes, int n_in,
                              void* d_out, int out_size) {
    const float4* boundary = (const float4*)d_in[0];
    const float2* xy       = (const float2*)d_in[1];
    const float2* dims     = (const float2*)d_in[2];
    const float*  cw       = (const float*)d_in[3];
    float* field = (float*)d_out;

    const int n = in_sizes[3];          // N_RECTS

    // d_out is poisoned; zero it (vectorized).
    int n4 = out_size / 4;
    zero_field_kernel4<<<(n4 + 255) / 256, 256>>>((float4*)field, n4);

    // 2 threads per rect
    int threads_total = 2 * n;
    charge_scatter_kernel<<<(threads_total + 255) / 256, 256>>>(
        boundary, xy, dims, cw, field, n);
}

// round 7
// speedup vs baseline: 1.3145x; 1.1572x over previous
#include <cuda_runtime.h>
#include <cstdint>

// field[i,j] = sum_n w_n * ox_n[i] * oy_n[j] / (lx*ly)
// dims < 3/G per axis -> each rect overlaps at most 4 consecutive cells/axis.
// 2 threads per rect; columns handled as ALIGNED pairs via red.global.add.v2.f32
// (8 bytes per L2 atomic op -> halves LTS atomic-ALU serialization).
//   ja0 = j0 & ~1. Footprint cols j0..j0+3 are inside aligned pairs ja0, ja0+2, ja0+4.
//   half 0 -> pairs {ja0, ja0+4}; half 1 -> pair {ja0+2}.

#define G 256

__global__ void zero_field_kernel4(float4* __restrict__ out, int n4) {
    int i = blockIdx.x * blockDim.x + threadIdx.x;
    if (i < n4) out[i] = make_float4(0.f, 0.f, 0.f, 0.f);
}

__device__ __forceinline__ void red_v2(float* addr, float v0, float v1) {
    asm volatile("red.global.add.v2.f32 [%0], {%1, %2};"
                 :: "l"(addr), "f"(v0), "f"(v1) : "memory");
}

__global__ void __launch_bounds__(256) charge_scatter_kernel(
    const float4* __restrict__ boundary,  // [xmin, ymin, xmax, ymax]
    const float2* __restrict__ xy,        // [N]
    const float2* __restrict__ dims,      // [N]
    const float* __restrict__ cw,         // [N]
    float* __restrict__ field,            // [G*G]
    int n)
{
    int t = blockIdx.x * blockDim.x + threadIdx.x;
    int r = t >> 1;          // rect index
    int half = t & 1;
    if (r >= n) return;

    const float4 b = *boundary;
    const float xmin = b.x, ymin = b.y;
    const float lx = (b.z - b.x) * (1.0f / G);
    const float ly = (b.w - b.y) * (1.0f / G);
    const float inv_lx = __frcp_rn(lx);   // exact: lx = 2^-8
    const float inv_ly = __frcp_rn(ly);

    const float2 p = xy[r];
    const float2 d = dims[r];
    const float bx0 = p.x;
    const float by0 = p.y;
    const float bx1 = bx0 + d.x;
    const float by1 = by0 + d.y;
    const float scale = cw[r] * inv_lx * inv_ly;

    int i0 = (int)floorf((bx0 - xmin) * inv_lx);
    int j0 = (int)floorf((by0 - ymin) * inv_ly);
    i0 = max(i0, 0);
    j0 = max(j0, 0);
    const int i1 = min(i0 + 3, G - 1);
    const int ja0 = j0 & ~1;             // aligned pair base

    // This thread's aligned column pairs
    int pb0, pb1;        // pair bases (pb1 < 0 => unused)
    if (half == 0) { pb0 = ja0;     pb1 = ja0 + 4; }
    else           { pb0 = ja0 + 2; pb1 = -1;      }

    // y overlap for a column (0 outside grid / footprint)
    auto oy = [&](int j) -> float {
        if (j >= G) return 0.0f;
        float gy0 = ymin + (float)j * ly;
        return fmaxf(fminf(gy0 + ly, by1) - fmaxf(gy0, by0), 0.0f);
    };

    float a0 = 0.f, a1 = 0.f, b0v = 0.f, b1v = 0.f;
    bool use0 = false, use1 = false;
    if (pb0 < G) {
        a0 = oy(pb0); a1 = oy(pb0 + 1);
        use0 = (a0 != 0.0f) || (a1 != 0.0f);
    }
    if (pb1 >= 0 && pb1 < G) {
        b0v = oy(pb1); b1v = oy(pb1 + 1);
        use1 = (b0v != 0.0f) || (b1v != 0.0f);
    }
    if (!use0 && !use1) return;

    for (int i = i0; i <= i1; i++) {
        float gx0 = xmin + (float)i * lx;
        float ox = fmaxf(fminf(gx0 + lx, bx1) - fmaxf(gx0, bx0), 0.0f);
        float sx = scale * ox;
        if (sx == 0.0f) continue;
        float* rowbase = field + i * G;
        if (use0) red_v2(rowbase + pb0, sx * a0, sx * a1);
        if (use1) red_v2(rowbase + pb1, sx * b0v, sx * b1v);
    }
}

extern "C" void kernel_launch(void* const* d_in, const int* in_sizes, int n_in,
                              void* d_out, int out_size) {
    const float4* boundary = (const float4*)d_in[0];
    const float2* xy       = (const float2*)d_in[1];
    const float2* dims     = (const float2*)d_in[2];
    const float*  cw       = (const float*)d_in[3];
    float* field = (float*)d_out;

    const int n = in_sizes[3];          // N_RECTS

    int n4 = out_size / 4;
    zero_field_kernel4<<<(n4 + 255) / 256, 256>>>((float4*)field, n4);

    int threads_total = 2 * n;
    charge_scatter_kernel<<<(threads_total + 255) / 256, 256>>>(
        boundary, xy, dims, cw, field, n);
}

// round 8
// speedup vs baseline: 1.3896x; 1.0571x over previous
#include <cuda_runtime.h>
#include <cstdint>

// field[i,j] = sum_n w_n * ox_n[i] * oy_n[j] / (lx*ly)
// dims < 3/G per axis -> footprint is <=4x4 cells.
// Columns handled as ALIGNED QUADS via red.global.add.v4.f32 (16B per LTS op).
//   jq = j0 & ~3 ; footprint cols lie in quads {jq, jq+4}; quads never straddle
//   the grid edge (G % 4 == 0), so no per-column bounds checks.
// 2 threads per rect, split by ROW PARITY (balanced: avg 2.5 rows -> 1.5/1.0).

#define G 256

__global__ void zero_field_kernel4(float4* __restrict__ out, int n4) {
    int i = blockIdx.x * blockDim.x + threadIdx.x;
    if (i < n4) out[i] = make_float4(0.f, 0.f, 0.f, 0.f);
}

__device__ __forceinline__ void red_v4(float* addr, float v0, float v1, float v2, float v3) {
    asm volatile("red.global.add.v4.f32 [%0], {%1, %2, %3, %4};"
                 :: "l"(addr), "f"(v0), "f"(v1), "f"(v2), "f"(v3) : "memory");
}

__global__ void __launch_bounds__(256) charge_scatter_kernel(
    const float4* __restrict__ boundary,  // [xmin, ymin, xmax, ymax]
    const float2* __restrict__ xy,        // [N]
    const float2* __restrict__ dims,      // [N]
    const float* __restrict__ cw,         // [N]
    float* __restrict__ field,            // [G*G]
    int n)
{
    int t = blockIdx.x * blockDim.x + threadIdx.x;
    int r = t >> 1;          // rect index
    int half = t & 1;        // row parity this thread owns
    if (r >= n) return;

    const float4 b = *boundary;
    const float xmin = b.x, ymin = b.y;
    const float lx = (b.z - b.x) * (1.0f / G);
    const float ly = (b.w - b.y) * (1.0f / G);
    const float inv_lx = __frcp_rn(lx);   // exact: lx = 2^-8
    const float inv_ly = __frcp_rn(ly);

    const float2 p = xy[r];
    const float2 d = dims[r];
    const float bx0 = p.x;
    const float by0 = p.y;
    const float bx1 = bx0 + d.x;
    const float by1 = by0 + d.y;
    const float scale = cw[r] * inv_lx * inv_ly;

    int i0 = (int)floorf((bx0 - xmin) * inv_lx);
    int j0 = (int)floorf((by0 - ymin) * inv_ly);
    i0 = max(i0, 0);
    j0 = max(j0, 0);
    const int i1 = min(i0 + 3, G - 1);
    const int jq0 = j0 & ~3;             // aligned quad base (<= 252)
    const int jq1 = jq0 + 4;

    // y overlaps for quad 0 (always inside grid)
    float q0[4], q1[4];
    #pragma unroll
    for (int k = 0; k < 4; k++) {
        float gy0 = ymin + (float)(jq0 + k) * ly;
        q0[k] = fmaxf(fminf(gy0 + ly, by1) - fmaxf(gy0, by0), 0.0f);
    }
    // quad 1 (may be outside grid or outside footprint)
    bool use1 = (jq1 < G);
    #pragma unroll
    for (int k = 0; k < 4; k++) {
        float gy0 = ymin + (float)(jq1 + k) * ly;
        q1[k] = use1 ? fmaxf(fminf(gy0 + ly, by1) - fmaxf(gy0, by0), 0.0f) : 0.0f;
    }
    const bool use0 = (q0[0] != 0.f) | (q0[1] != 0.f) | (q0[2] != 0.f) | (q0[3] != 0.f);
    use1 = use1 && ((q1[0] != 0.f) | (q1[1] != 0.f) | (q1[2] != 0.f) | (q1[3] != 0.f));
    if (!use0 && !use1) return;

    // Rows of this thread's parity: at most 2 of {i0+half, i0+half+2}
    #pragma unroll
    for (int step = 0; step < 2; step++) {
        int i = i0 + half + step * 2;
        if (i > i1) break;
        float gx0 = xmin + (float)i * lx;
        float ox = fmaxf(fminf(gx0 + lx, bx1) - fmaxf(gx0, bx0), 0.0f);
        float sx = scale * ox;
        if (sx == 0.0f) continue;
        float* rowbase = field + i * G;
        if (use0) red_v4(rowbase + jq0, sx * q0[0], sx * q0[1], sx * q0[2], sx * q0[3]);
        if (use1) red_v4(rowbase + jq1, sx * q1[0], sx * q1[1], sx * q1[2], sx * q1[3]);
    }
}

extern "C" void kernel_launch(void* const* d_in, const int* in_sizes, int n_in,
                              void* d_out, int out_size) {
    const float4* boundary = (const float4*)d_in[0];
    const float2* xy       = (const float2*)d_in[1];
    const float2* dims     = (const float2*)d_in[2];
    const float*  cw       = (const float*)d_in[3];
    float* field = (float*)d_out;

    const int n = in_sizes[3];          // N_RECTS

    int n4 = out_size / 4;
    zero_field_kernel4<<<(n4 + 255) / 256, 256>>>((float4*)field, n4);

    int threads_total = 2 * n;
    charge_scatter_kernel<<<(threads_total + 255) / 256, 256>>>(
        boundary, xy, dims, cw, field, n);
}

// round 9
// speedup vs baseline: 1.5970x; 1.1493x over previous
#include <cuda_runtime.h>
#include <cstdint>

// field[i,j] = sum_n w_n * ox_n[i] * oy_n[j] / (lx*ly)
// dims < 3/G per axis -> footprint <= 4x4 cells.
// 1 thread per rect (REDs are fire-and-forget -> no scoreboard chain; dedupe
// all per-rect loads/setup). Cell-unit coordinates: u = (x - min) * G/extent,
// overlap/lx = clamp(min(u1, c+1) - max(u0, c), 0)  -> field += w * oxu * oyu.
// Columns as ALIGNED QUADS via red.global.add.v4.f32 (quads never straddle
// the grid edge since G % 4 == 0).

#define G 256

__global__ void zero_field_kernel4(float4* __restrict__ out, int n4) {
    int i = blockIdx.x * blockDim.x + threadIdx.x;
    if (i < n4) out[i] = make_float4(0.f, 0.f, 0.f, 0.f);
}

__device__ __forceinline__ void red_v4(float* addr, float v0, float v1, float v2, float v3) {
    asm volatile("red.global.add.v4.f32 [%0], {%1, %2, %3, %4};"
                 :: "l"(addr), "f"(v0), "f"(v1), "f"(v2), "f"(v3) : "memory");
}

__global__ void __launch_bounds__(256) charge_scatter_kernel(
    const float4* __restrict__ boundary,  // [xmin, ymin, xmax, ymax]
    const float2* __restrict__ xy,        // [N]
    const float2* __restrict__ dims,      // [N]
    const float* __restrict__ cw,         // [N]
    float* __restrict__ field,            // [G*G]
    int n)
{
    int r = blockIdx.x * blockDim.x + threadIdx.x;
    if (r >= n) return;

    const float4 b = *boundary;
    const float inv_lx = __frcp_rn((b.z - b.x) * (1.0f / G));  // exact: lx = 2^-8
    const float inv_ly = __frcp_rn((b.w - b.y) * (1.0f / G));

    const float2 p = xy[r];
    const float2 d = dims[r];
    const float w = cw[r];

    // Cell-unit coordinates
    const float x0u = (p.x - b.x) * inv_lx;
    const float x1u = (p.x + d.x - b.x) * inv_lx;
    const float y0u = (p.y - b.y) * inv_ly;
    const float y1u = (p.y + d.y - b.y) * inv_ly;

    int i0 = max((int)floorf(x0u), 0);
    int j0 = max((int)floorf(y0u), 0);
    const int jq0 = j0 & ~3;              // aligned quad base (<= 252)
    const int jq1 = jq0 + 4;
    const bool have1 = (jq1 < G);

    // y overlaps (cell units) for both quads
    float q0[4], q1[4];
    #pragma unroll
    for (int k = 0; k < 4; k++) {
        float c = (float)(jq0 + k);
        q0[k] = fmaxf(fminf(y1u, c + 1.0f) - fmaxf(y0u, c), 0.0f);
    }
    #pragma unroll
    for (int k = 0; k < 4; k++) {
        float c = (float)(jq1 + k);
        q1[k] = have1 ? fmaxf(fminf(y1u, c + 1.0f) - fmaxf(y0u, c), 0.0f) : 0.0f;
    }
    const bool use0 = (q0[0] != 0.f) | (q0[1] != 0.f) | (q0[2] != 0.f) | (q0[3] != 0.f);
    const bool use1 = have1 && ((q1[0] != 0.f) | (q1[1] != 0.f) | (q1[2] != 0.f) | (q1[3] != 0.f));
    if (!use0 && !use1) return;

    // All 4 candidate rows, fully unrolled (predicated REDs)
    #pragma unroll
    for (int s = 0; s < 4; s++) {
        int i = i0 + s;
        float fi = (float)i;
        float oxu = fmaxf(fminf(x1u, fi + 1.0f) - fmaxf(x0u, fi), 0.0f);
        float sx = w * oxu;
        if (i < G && sx != 0.0f) {
            float* rowbase = field + i * G;
            if (use0) red_v4(rowbase + jq0, sx * q0[0], sx * q0[1], sx * q0[2], sx * q0[3]);
            if (use1) red_v4(rowbase + jq1, sx * q1[0], sx * q1[1], sx * q1[2], sx * q1[3]);
        }
    }
}

extern "C" void kernel_launch(void* const* d_in, const int* in_sizes, int n_in,
                              void* d_out, int out_size) {
    const float4* boundary = (const float4*)d_in[0];
    const float2* xy       = (const float2*)d_in[1];
    const float2* dims     = (const float2*)d_in[2];
    const float*  cw       = (const float*)d_in[3];
    float* field = (float*)d_out;

    const int n = in_sizes[3];          // N_RECTS

    int n4 = out_size / 4;
    zero_field_kernel4<<<(n4 + 255) / 256, 256>>>((float4*)field, n4);

    charge_scatter_kernel<<<(n + 255) / 256, 256>>>(boundary, xy, dims, cw, field, n);
}